// round 17
// baseline (speedup 1.0000x reference)
#include <cuda_runtime.h>
#include <cuda_fp16.h>
#include <math.h>
#include <stdint.h>

// Problem constants
#define BDIM 2
#define SDIM 2048
#define DDIM 1024
#define NHEAD 16
#define HDIM 64
#define MDIM 4096
#define ROWS (BDIM*SDIM)          // 4096 token rows
#define QKVC (NHEAD*3*HDIM)       // 3072 packed qkv columns

// ---------------- scratch (device globals; no allocation allowed) ----------
__device__ __half g_ln  [ROWS*DDIM];
__device__ __half g_wqt [QKVC*DDIM];
__device__ __half g_w1t [MDIM*DDIM];
__device__ __half g_w2t [DDIM*MDIM];
__device__ __half g_qkv [ROWS*QKVC];
__device__ float  g_atto[BDIM*NHEAD*SDIM*HDIM];
__device__ float  g_wsum[DDIM];
__device__ float  g_x1  [ROWS*DDIM];
__device__ __half g_h   [ROWS*MDIM];

// ============================ helpers =======================================
__device__ __forceinline__ uint32_t smem_u32(const void* p) {
    uint32_t a;
    asm("{ .reg .u64 t; cvta.to.shared.u64 t, %1; cvt.u32.u64 %0, t; }"
        : "=r"(a) : "l"(p));
    return a;
}
__device__ __forceinline__ void cp16(uint32_t dst, const void* src) {
    asm volatile("cp.async.cg.shared.global [%0], [%1], 16;" :: "r"(dst), "l"(src));
}
__device__ __forceinline__ float gelu_exact(float v) {
    return 0.5f * v * (1.0f + erff(v * 0.70710678118654752440f));
}
__device__ __forceinline__ uint32_t pack_h2(float x, float y) {
    __half2 h = __floats2half2_rn(x, y);
    return *(uint32_t*)&h;
}

#define MMA_F16(c, a, b) \
    asm volatile("mma.sync.aligned.m16n8k16.row.col.f32.f16.f16.f32 " \
        "{%0,%1,%2,%3}, {%4,%5,%6,%7}, {%8,%9}, {%0,%1,%2,%3};" \
        : "+f"((c)[0]), "+f"((c)[1]), "+f"((c)[2]), "+f"((c)[3]) \
        : "r"((a)[0]), "r"((a)[1]), "r"((a)[2]), "r"((a)[3]), \
          "r"((b)[0]), "r"((b)[1]))

#define LDSM_X4(r0, r1, r2, r3, addr) \
    asm volatile("ldmatrix.sync.aligned.m8n8.x4.shared.b16 {%0,%1,%2,%3}, [%4];" \
        : "=r"(r0), "=r"(r1), "=r"(r2), "=r"(r3) : "r"(addr))
#define LDSM_X4T(r0, r1, r2, r3, addr) \
    asm volatile("ldmatrix.sync.aligned.m8n8.x4.trans.shared.b16 {%0,%1,%2,%3}, [%4];" \
        : "=r"(r0), "=r"(r1), "=r"(r2), "=r"(r3) : "r"(addr))

// ========== fp16 HMMA GEMM: C[M,N] = A[M,K] * Bt[N,K]^T =====================
// CTA 128x128, 128 thr (4 warps 2x2 -> warp tile 64x64, 1:4 LDSM:MMA ratio).
// K staged at 32, 5-slot cp.async pipeline (4 in flight), 1 sync/stage.
// 2 CTAs/SM. Pitch 40 halves: conflict-free ldmatrix.
#define GP 40
#define STAGE_H (128*GP)
#define NSTG 5
#define GEMM_SMEM (2*NSTG*STAGE_H*2)          // 102400 bytes

// EPI: 1 = +bias, gelu -> half; 2 = +bias +res -> float; 3 = plain -> half
template<int EPI>
__global__ __launch_bounds__(128, 2)
void mma_gemm(const __half* __restrict__ A, const __half* __restrict__ Bt,
              void* __restrict__ Cv, int M, int N, int K,
              const float* __restrict__ bias, const float* __restrict__ res)
{
    extern __shared__ __half smh[];
    __half* As = smh;                  // [NSTG][STAGE_H]
    __half* Bs = smh + NSTG * STAGE_H;

    const int tid = threadIdx.x;
    const int wid = tid >> 5, lane = tid & 31;
    const int bm = blockIdx.y * 128, bn = blockIdx.x * 128;
    const int mbase = (wid >> 1) * 64;
    const int nbase = (wid & 1) * 64;
    const int q = lane >> 2, r4 = lane & 3;
    const int lr16 = lane & 15;              // A ldmatrix row-in-16
    const int lc8  = (lane >> 4) << 3;       // A ldmatrix col half-offset
    const int bRow = ((lane >> 4) << 3) + (lane & 7);   // B x4 row
    const int bCol = ((lane >> 3) & 1) << 3;            // B x4 col half-offset

    const uint32_t sA = smem_u32(As);
    const uint32_t sB = smem_u32(Bs);
    const int nst = K >> 5;

    auto load_stage = [&](int s) {
        int slot = s - (s / NSTG) * NSTG;
        int k0 = s << 5;
        const __half* Ag = A + (size_t)bm * K + k0;
        const __half* Bg = Bt + (size_t)bn * K + k0;
        uint32_t ab = sA + slot * (STAGE_H * 2);
        uint32_t bb = sB + slot * (STAGE_H * 2);
        #pragma unroll
        for (int i = 0; i < 4; ++i) {
            int linear = i * 128 + tid;          // 0..511
            int row = linear >> 2, c = linear & 3;
            uint32_t off = (uint32_t)(row * GP + c * 8) * 2;
            cp16(ab + off, Ag + (size_t)row * K + c * 8);
            cp16(bb + off, Bg + (size_t)row * K + c * 8);
        }
        asm volatile("cp.async.commit_group;" ::: "memory");
    };

    float c[4][8][4];
    #pragma unroll
    for (int mt = 0; mt < 4; ++mt)
        #pragma unroll
        for (int nt = 0; nt < 8; ++nt)
            #pragma unroll
            for (int j = 0; j < 4; ++j) c[mt][nt][j] = 0.f;

    load_stage(0); load_stage(1); load_stage(2); load_stage(3);

    for (int s = 0; s < nst; ++s) {
        int slot = s - (s / NSTG) * NSTG;
        asm volatile("cp.async.wait_group 3;" ::: "memory");
        __syncthreads();
        if (s + 4 < nst) load_stage(s + 4);
        else asm volatile("cp.async.commit_group;" ::: "memory");

        uint32_t aA = sA + slot * (STAGE_H * 2);
        uint32_t aB = sB + slot * (STAGE_H * 2);
        #pragma unroll
        for (int kk = 0; kk < 2; ++kk) {
            int kb = kk * 16;
            uint32_t a[4][4];
            #pragma unroll
            for (int mt = 0; mt < 4; ++mt) {
                uint32_t ad = aA +
                    (uint32_t)((mbase + mt * 16 + lr16) * GP + kb + lc8) * 2;
                LDSM_X4(a[mt][0], a[mt][1], a[mt][2], a[mt][3], ad);
            }
            uint32_t b[8][2];
            #pragma unroll
            for (int ntp = 0; ntp < 4; ++ntp) {
                uint32_t bd = aB +
                    (uint32_t)((nbase + ntp * 16 + bRow) * GP + kb + bCol) * 2;
                LDSM_X4(b[2*ntp][0], b[2*ntp][1], b[2*ntp+1][0], b[2*ntp+1][1], bd);
            }
            #pragma unroll
            for (int mt = 0; mt < 4; ++mt)
                #pragma unroll
                for (int nt = 0; nt < 8; ++nt)
                    MMA_F16(c[mt][nt], a[mt], b[nt]);
        }
    }

    #pragma unroll
    for (int mt = 0; mt < 4; ++mt) {
        #pragma unroll
        for (int nt = 0; nt < 8; ++nt) {
            int row0 = bm + mbase + mt * 16 + q;
            int col  = bn + nbase + nt * 8 + r4 * 2;
            #pragma unroll
            for (int h = 0; h < 2; ++h) {
                int row = row0 + h * 8;
                float vx = c[mt][nt][2 * h], vy = c[mt][nt][2 * h + 1];
                if (EPI == 1) {
                    vx = gelu_exact(vx + bias[col]);
                    vy = gelu_exact(vy + bias[col + 1]);
                    __half* C = (__half*)Cv;
                    *(uint32_t*)(C + (size_t)row * N + col) = pack_h2(vx, vy);
                } else if (EPI == 2) {
                    const float* rp = res + (size_t)row * N + col;
                    vx += bias[col] + rp[0];
                    vy += bias[col + 1] + rp[1];
                    float* C = (float*)Cv;
                    *(float2*)(C + (size_t)row * N + col) = make_float2(vx, vy);
                } else {
                    __half* C = (__half*)Cv;
                    *(uint32_t*)(C + (size_t)row * N + col) = pack_h2(vx, vy);
                }
            }
        }
    }
}

// ---------------- layernorm (ddof=1, eps=1e-4) -> half ----------------------
__global__ __launch_bounds__(256) void ln_kernel(
    const float* __restrict__ x, const float* __restrict__ w,
    const float* __restrict__ bb, __half* __restrict__ y)
{
    int row = blockIdx.x;
    int t = threadIdx.x;
    const float4* xr = (const float4*)(x + (size_t)row * DDIM);
    float4 v = xr[t];

    __shared__ float red[8];
    __shared__ float s_mu, s_inv;

    float s = v.x + v.y + v.z + v.w;
    #pragma unroll
    for (int o = 16; o > 0; o >>= 1) s += __shfl_xor_sync(0xffffffffu, s, o);
    if ((t & 31) == 0) red[t >> 5] = s;
    __syncthreads();
    if (t == 0) {
        float tot = 0.f;
        #pragma unroll
        for (int i = 0; i < 8; ++i) tot += red[i];
        s_mu = tot * (1.0f / DDIM);
    }
    __syncthreads();
    float mu = s_mu;
    float dx = v.x - mu, dy = v.y - mu, dz = v.z - mu, dw = v.w - mu;
    float ss = dx*dx + dy*dy + dz*dz + dw*dw;
    #pragma unroll
    for (int o = 16; o > 0; o >>= 1) ss += __shfl_xor_sync(0xffffffffu, ss, o);
    __syncthreads();
    if ((t & 31) == 0) red[t >> 5] = ss;
    __syncthreads();
    if (t == 0) {
        float tot = 0.f;
        #pragma unroll
        for (int i = 0; i < 8; ++i) tot += red[i];
        s_inv = rsqrtf(tot * (1.0f / (DDIM - 1)) + 1e-4f);
    }
    __syncthreads();
    float inv = s_inv;
    float4 wv = ((const float4*)w)[t];
    float4 bv = ((const float4*)bb)[t];
    uint2 o;
    o.x = pack_h2(dx * inv * wv.x + bv.x, dy * inv * wv.y + bv.y);
    o.y = pack_h2(dz * inv * wv.z + bv.z, dw * inv * wv.w + bv.w);
    *(uint2*)(y + (size_t)row * DDIM + t * 4) = o;
}

// ------------- transpose [K,N] float -> [N,K] half --------------------------
__global__ __launch_bounds__(256) void transpose_h(
    const float* __restrict__ in, __half* __restrict__ out, int K, int N)
{
    __shared__ float t[32][33];
    int k0 = blockIdx.y * 32, n0 = blockIdx.x * 32;
    int tx = threadIdx.x, ty = threadIdx.y;
    #pragma unroll
    for (int r = 0; r < 32; r += 8)
        t[ty + r][tx] = in[(size_t)(k0 + ty + r) * N + n0 + tx];
    __syncthreads();
    #pragma unroll
    for (int r = 0; r < 32; r += 8)
        out[(size_t)(n0 + ty + r) * K + k0 + tx] = __float2half_rn(t[tx][ty + r]);
}

// ------- pack+transpose W_qkv[N,D,192] -> [(n*192+j), d] half ----------------
__global__ __launch_bounds__(256) void pack_wqkv_t(
    const float* __restrict__ W, __half* __restrict__ out)
{
    __shared__ float t[32][33];
    int j0 = blockIdx.x * 32, d0 = blockIdx.y * 32, n = blockIdx.z;
    int tx = threadIdx.x, ty = threadIdx.y;
    #pragma unroll
    for (int r = 0; r < 32; r += 8)
        t[ty + r][tx] = W[((size_t)n * DDIM + d0 + ty + r) * 192 + j0 + tx];
    __syncthreads();
    #pragma unroll
    for (int r = 0; r < 32; r += 8)
        out[((size_t)n * 192 + j0 + ty + r) * DDIM + d0 + tx] =
            __float2half_rn(t[tx][ty + r]);
}

// ---------------- w_sum[d] = sum_{n,h} W_out[n,h,d] -------------------------
__global__ __launch_bounds__(256) void wsum_kernel(
    const float* __restrict__ Wout, float* __restrict__ ws)
{
    int d = blockIdx.x * 256 + threadIdx.x;
    float s = 0.f;
    for (int i = 0; i < NHEAD * HDIM; ++i) s += Wout[(size_t)i * DDIM + d];
    ws[d] = s;
}

// ============ flash attention, fp16 HMMA + x4 ldmatrix ======================
// 128 q rows per CTA (256 thr / 8 warps), k-tiles of 64, double-buffered with
// register prefetch. Q fragments hoisted, P register-direct.
#define FPH 72
#define FLASH_SMEM ((128 + 256) * FPH * 2)   // Qs + 2*K + 2*V = 55296 bytes

__global__ __launch_bounds__(256) void flash_mma(
    const __half* __restrict__ qkv, float* __restrict__ atto)
{
    extern __shared__ __half smf[];
    __half* Qs = smf;                      // [128][FPH] Q, scaled
    __half* Kb = smf + 128 * FPH;          // [2][64][FPH] K row-major (j x h)
    __half* Vb = smf + 256 * FPH;          // [2][64][FPH] V row-major (j x h)

    const int qt = (int)gridDim.x - 1 - (int)blockIdx.x;   // longest first
    const int n = blockIdx.y, b = blockIdx.z;
    const int tid = threadIdx.x, wid = tid >> 5, lane = tid & 31;
    const int q = lane >> 2, r4 = lane & 3;
    const int lr16 = lane & 15, lc8 = (lane >> 4) << 3;
    const int bRow = ((lane >> 4) << 3) + (lane & 7);
    const int bCol = ((lane >> 3) & 1) << 3;
    const int mrow = wid * 16;
    const __half* base = qkv + (size_t)b * SDIM * QKVC + n * 192;
    const __half2 qscale = __float2half2_rn(0.125f);   // exact

    // load Q tile (128 rows), scaled
    #pragma unroll
    for (int i = 0; i < 4; ++i) {
        int linear = i * 256 + tid;
        int row = linear >> 3, c8 = (linear & 7) * 8;
        uint4 v = *(const uint4*)(base + (size_t)(qt * 128 + row) * QKVC + c8);
        __half2* h = (__half2*)&v;
        h[0] = __hmul2(h[0], qscale); h[1] = __hmul2(h[1], qscale);
        h[2] = __hmul2(h[2], qscale); h[3] = __hmul2(h[3], qscale);
        *(uint4*)(Qs + row * FPH + c8) = v;
    }

    uint4 kr[2], vr[2];
    auto ldg_tile = [&](int kt) {
        #pragma unroll
        for (int i = 0; i < 2; ++i) {
            int linear = i * 256 + tid;
            int row = linear >> 3, c8 = (linear & 7) * 8;
            const __half* rb = base + (size_t)(kt * 64 + row) * QKVC;
            kr[i] = *(const uint4*)(rb + 64 + c8);
            vr[i] = *(const uint4*)(rb + 128 + c8);
        }
    };
    auto sts_tile = [&](int buf) {
        __half* Ksb = Kb + buf * 64 * FPH;
        __half* Vsb = Vb + buf * 64 * FPH;
        #pragma unroll
        for (int i = 0; i < 2; ++i) {
            int linear = i * 256 + tid;
            int row = linear >> 3, c8 = (linear & 7) * 8;
            *(uint4*)(Ksb + row * FPH + c8) = kr[i];
            *(uint4*)(Vsb + row * FPH + c8) = vr[i];
        }
    };

    float m0 = -INFINITY, m1 = -INFINITY, l0 = 0.f, l1 = 0.f;
    float o[8][4];
    #pragma unroll
    for (int nt = 0; nt < 8; ++nt)
        o[nt][0] = o[nt][1] = o[nt][2] = o[nt][3] = 0.f;

    ldg_tile(0);
    sts_tile(0);
    __syncthreads();

    // Q A-fragments: loop-invariant, load once
    uint32_t aq[4][4];
    {
        uint32_t qb = smem_u32(Qs);
        #pragma unroll
        for (int kk = 0; kk < 4; ++kk) {
            uint32_t ad = qb + (uint32_t)((mrow + lr16) * FPH + kk * 16 + lc8) * 2;
            LDSM_X4(aq[kk][0], aq[kk][1], aq[kk][2], aq[kk][3], ad);
        }
    }

    const uint32_t kb0 = smem_u32(Kb);
    const uint32_t vb0 = smem_u32(Vb);
    const int kend = 2 * qt + 1;

    for (int kt = 0; kt <= kend; ++kt) {
        int cur = kt & 1;
        if (kt < kend) ldg_tile(kt + 1);          // prefetch into registers

        // warp fully masked on this tile? (all j > all i) — skip compute
        bool active = (kt * 64) <= (qt * 128 + mrow + 15);

        if (active) {
            uint32_t ks = kb0 + cur * (64 * FPH * 2);
            uint32_t vs = vb0 + cur * (64 * FPH * 2);

            // S = Q @ K^T  (16x64 per warp, 4 k16 steps)
            float c[8][4];
            #pragma unroll
            for (int nt = 0; nt < 8; ++nt)
                c[nt][0] = c[nt][1] = c[nt][2] = c[nt][3] = 0.f;
            #pragma unroll
            for (int kk = 0; kk < 4; ++kk) {
                int kb = kk * 16;
                #pragma unroll
                for (int ntp = 0; ntp < 4; ++ntp) {
                    uint32_t bd = ks +
                        (uint32_t)((ntp * 16 + bRow) * FPH + kb + bCol) * 2;
                    uint32_t bf[4];
                    LDSM_X4(bf[0], bf[1], bf[2], bf[3], bd);
                    MMA_F16(c[2*ntp],   aq[kk], bf);
                    MMA_F16(c[2*ntp+1], aq[kk], bf + 2);
                }
            }

            // causal mask (global indices) — only near the diagonal
            if (kt * 64 + 63 > qt * 128 + mrow) {
                int i0 = qt * 128 + mrow + q;
                #pragma unroll
                for (int nt = 0; nt < 8; ++nt) {
                    int j0 = kt * 64 + nt * 8 + 2 * r4;
                    if (j0     > i0)     c[nt][0] = -INFINITY;
                    if (j0 + 1 > i0)     c[nt][1] = -INFINITY;
                    if (j0     > i0 + 8) c[nt][2] = -INFINITY;
                    if (j0 + 1 > i0 + 8) c[nt][3] = -INFINITY;
                }
            }

            // online softmax; rows live in 4 lanes (xor 1,2)
            float rm0 = -INFINITY, rm1 = -INFINITY;
            #pragma unroll
            for (int nt = 0; nt < 8; ++nt) {
                rm0 = fmaxf(rm0, fmaxf(c[nt][0], c[nt][1]));
                rm1 = fmaxf(rm1, fmaxf(c[nt][2], c[nt][3]));
            }
            rm0 = fmaxf(rm0, __shfl_xor_sync(0xffffffffu, rm0, 1));
            rm0 = fmaxf(rm0, __shfl_xor_sync(0xffffffffu, rm0, 2));
            rm1 = fmaxf(rm1, __shfl_xor_sync(0xffffffffu, rm1, 1));
            rm1 = fmaxf(rm1, __shfl_xor_sync(0xffffffffu, rm1, 2));
            float mn0 = fmaxf(m0, rm0), mn1 = fmaxf(m1, rm1);
            float al0 = __expf(m0 - mn0), al1 = __expf(m1 - mn1);
            m0 = mn0; m1 = mn1;
            float rs0 = 0.f, rs1 = 0.f;
            #pragma unroll
            for (int nt = 0; nt < 8; ++nt) {
                c[nt][0] = __expf(c[nt][0] - mn0); rs0 += c[nt][0];
                c[nt][1] = __expf(c[nt][1] - mn0); rs0 += c[nt][1];
                c[nt][2] = __expf(c[nt][2] - mn1); rs1 += c[nt][2];
                c[nt][3] = __expf(c[nt][3] - mn1); rs1 += c[nt][3];
            }
            rs0 += __shfl_xor_sync(0xffffffffu, rs0, 1);
            rs0 += __shfl_xor_sync(0xffffffffu, rs0, 2);
            rs1 += __shfl_xor_sync(0xffffffffu, rs1, 1);
            rs1 += __shfl_xor_sync(0xffffffffu, rs1, 2);
            l0 = l0 * al0 + rs0;
            l1 = l1 * al1 + rs1;
            #pragma unroll
            for (int nt = 0; nt < 8; ++nt) {
                o[nt][0] *= al0; o[nt][1] *= al0;
                o[nt][2] *= al1; o[nt][3] *= al1;
            }

            // O += P @ V — P register-direct A-fragments; V via ldmatrix.x4.trans
            #pragma unroll
            for (int kk = 0; kk < 4; ++kk) {
                int kb = kk * 16;
                uint32_t a[4] = {pack_h2(c[2*kk][0],   c[2*kk][1]),
                                 pack_h2(c[2*kk][2],   c[2*kk][3]),
                                 pack_h2(c[2*kk+1][0], c[2*kk+1][1]),
                                 pack_h2(c[2*kk+1][2], c[2*kk+1][3])};
                #pragma unroll
                for (int ntp = 0; ntp < 4; ++ntp) {
                    uint32_t vd = vs +
                        (uint32_t)((kb + lr16) * FPH + ntp * 16 + lc8) * 2;
                    uint32_t bf[4];
                    LDSM_X4T(bf[0], bf[1], bf[2], bf[3], vd);
                    MMA_F16(o[2*ntp],   a, bf);
                    MMA_F16(o[2*ntp+1], a, bf + 2);
                }
            }
        }

        if (kt < kend) {
            sts_tile(cur ^ 1);
            __syncthreads();
        }
    }

    // normalize + store (b,n,s,h) fp32
    float inv0 = 1.0f / l0, inv1 = 1.0f / l1;
    float* ob = atto + ((size_t)(b * NHEAD + n) * SDIM + qt * 128) * HDIM;
    int row0 = mrow + q;
    #pragma unroll
    for (int nt = 0; nt < 8; ++nt) {
        int col = nt * 8 + 2 * r4;
        *(float2*)(ob + (size_t)row0 * HDIM + col) =
            make_float2(o[nt][0] * inv0, o[nt][1] * inv0);
        *(float2*)(ob + (size_t)(row0 + 8) * HDIM + col) =
            make_float2(o[nt][2] * inv1, o[nt][3] * inv1);
    }
}

// ------- residual + torch-reinterpretation "projection" ---------------------
__global__ void resid_attn(const float* __restrict__ x,
                           const float* __restrict__ atto,
                           const float* __restrict__ wsum,
                           float* __restrict__ x1)
{
    __shared__ float tile[32][33];
    int b = blockIdx.z;
    int d0 = blockIdx.x * 32, s0 = blockIdx.y * 32;
    int tx = threadIdx.x, ty = threadIdx.y;
    const float* ab = atto + (size_t)b * (DDIM * SDIM);
    #pragma unroll
    for (int r = 0; r < 32; r += 8) {
        int d = d0 + ty + r, s = s0 + tx;
        tile[ty + r][tx] = ab[(size_t)d * SDIM + s];
    }
    __syncthreads();
    #pragma unroll
    for (int r = 0; r < 32; r += 8) {
        int s = s0 + ty + r, d = d0 + tx;
        size_t idx = ((size_t)b * SDIM + s) * DDIM + d;
        x1[idx] = x[idx] + tile[tx][ty + r] * wsum[d];
    }
}

// ---------------------------------------------------------------------------
extern "C" void kernel_launch(void* const* d_in, const int* in_sizes, int n_in,
                              void* d_out, int out_size)
{
    const float* x    = (const float*)d_in[0];
    const float* Wqkv = (const float*)d_in[1];
    const float* Wout = (const float*)d_in[2];
    const float* ln1w = (const float*)d_in[3];
    const float* ln1b = (const float*)d_in[4];
    const float* ln2w = (const float*)d_in[5];
    const float* ln2b = (const float*)d_in[6];
    const float* W1   = (const float*)d_in[7];
    const float* b1   = (const float*)d_in[8];
    const float* W2   = (const float*)d_in[9];
    const float* b2   = (const float*)d_in[10];
    float* out = (float*)d_out;

    __half *p_ln, *p_wqt, *p_w1t, *p_w2t, *p_qkv, *p_h;
    float *p_atto, *p_wsum, *p_x1;
    cudaGetSymbolAddress((void**)&p_ln,   g_ln);
    cudaGetSymbolAddress((void**)&p_wqt,  g_wqt);
    cudaGetSymbolAddress((void**)&p_w1t,  g_w1t);
    cudaGetSymbolAddress((void**)&p_w2t,  g_w2t);
    cudaGetSymbolAddress((void**)&p_qkv,  g_qkv);
    cudaGetSymbolAddress((void**)&p_atto, g_atto);
    cudaGetSymbolAddress((void**)&p_wsum, g_wsum);
    cudaGetSymbolAddress((void**)&p_x1,   g_x1);
    cudaGetSymbolAddress((void**)&p_h,    g_h);

    cudaFuncSetAttribute(mma_gemm<1>, cudaFuncAttributeMaxDynamicSharedMemorySize, GEMM_SMEM);
    cudaFuncSetAttribute(mma_gemm<2>, cudaFuncAttributeMaxDynamicSharedMemorySize, GEMM_SMEM);
    cudaFuncSetAttribute(mma_gemm<3>, cudaFuncAttributeMaxDynamicSharedMemorySize, GEMM_SMEM);
    cudaFuncSetAttribute(flash_mma, cudaFuncAttributeMaxDynamicSharedMemorySize, FLASH_SMEM);

    // prep + ln1 (ordered so the QKV GEMM is the 4th launch -> ncu captures it)
    pack_wqkv_t<<<dim3(6, 32, 16), dim3(32, 8)>>>(Wqkv, p_wqt);
    wsum_kernel<<<DDIM / 256, 256>>>(Wout, p_wsum);
    ln_kernel<<<ROWS, 256>>>(x, ln1w, ln1b, p_ln);

    // QKV projection (fp16 HMMA, half out for flash) — launch #4
    mma_gemm<3><<<dim3(QKVC / 128, ROWS / 128), 128, GEMM_SMEM>>>(
        p_ln, p_wqt, p_qkv, ROWS, QKVC, DDIM, nullptr, nullptr);

    // weight transposes for the MLP (only needed before MLP1/MLP2)
    transpose_h<<<dim3(MDIM / 32, DDIM / 32), dim3(32, 8)>>>(W1, p_w1t, DDIM, MDIM);
    transpose_h<<<dim3(DDIM / 32, MDIM / 32), dim3(32, 8)>>>(W2, p_w2t, MDIM, DDIM);

    // attention (fp16 HMMA flash, 128-row q tiles)
    flash_mma<<<dim3(SDIM / 128, NHEAD, BDIM), 256, FLASH_SMEM>>>(p_qkv, p_atto);

    // residual + reinterpretation-projection
    resid_attn<<<dim3(DDIM / 32, SDIM / 32, BDIM), dim3(32, 8)>>>(
        x, p_atto, p_wsum, p_x1);

    // ln2
    ln_kernel<<<ROWS, 256>>>(p_x1, ln2w, ln2b, p_ln);

    // MLP (fp16 HMMA)
    mma_gemm<1><<<dim3(MDIM / 128, ROWS / 128), 128, GEMM_SMEM>>>(
        p_ln, p_w1t, p_h, ROWS, MDIM, DDIM, b1, nullptr);
    mma_gemm<2><<<dim3(DDIM / 128, ROWS / 128), 128, GEMM_SMEM>>>(
        p_h, p_w2t, out, ROWS, DDIM, MDIM, b2, p_x1);
}